// round 7
// baseline (speedup 1.0000x reference)
#include <cuda_runtime.h>
#include <cuda_bf16.h>
#include <math.h>
#include <cstdint>

// Problem constants
#define B_     8192
#define DIN    512
#define UU     256
#define MM     50
#define BMROWS (B_ * MM)     // 409600

// ---------------- scratch (device globals; no allocation allowed) ----------
__device__ float g_hb[B_ * UU];
__device__ float g_scores[BMROWS];
__device__ float g_text[B_ * UU];
__device__ float g_F[B_ * UU];
__device__ float g_O[B_ * UU];
__device__ float g_T[B_ * UU];

// prepped weights, bf16 hi/lo, [N][K] row-major regions:
//   OW_SA  [256][256]   W_sa^T
//   OW_HA  [256][256]   W_ha^T
//   OW_FOT [768][512]   n: F|O|T,  k: text(256)|h(256)
//   OW_KHH [768][1024]  n: k|hx|hv, k: X(512)|h(256)|V(256)
#define OW_SA  0
#define OW_HA  65536
#define OW_FOT 131072
#define OW_KHH 524288
#define WTOT   1310720
__device__ __nv_bfloat16 g_Wh[WTOT];
__device__ __nv_bfloat16 g_Wl[WTOT];

// ======================= low-level helpers ==================================
static __device__ __forceinline__ uint32_t smem_u32(const void* p) {
    uint32_t a;
    asm("{ .reg .u64 t; cvta.to.shared.u64 t, %1; cvt.u32.u64 %0, t; }"
        : "=r"(a) : "l"(p));
    return a;
}

static __device__ __forceinline__ void ldsm4(uint32_t* r, uint32_t a) {
    asm volatile("ldmatrix.sync.aligned.m8n8.x4.shared.b16 {%0,%1,%2,%3}, [%4];"
                 : "=r"(r[0]), "=r"(r[1]), "=r"(r[2]), "=r"(r[3]) : "r"(a));
}

static __device__ __forceinline__ void mma_bf16(float* c, const uint32_t* a,
                                                const uint32_t* b) {
    asm volatile(
        "mma.sync.aligned.m16n8k16.row.col.f32.bf16.bf16.f32 "
        "{%0,%1,%2,%3}, {%4,%5,%6,%7}, {%8,%9}, {%0,%1,%2,%3};"
        : "+f"(c[0]), "+f"(c[1]), "+f"(c[2]), "+f"(c[3])
        : "r"(a[0]), "r"(a[1]), "r"(a[2]), "r"(a[3]), "r"(b[0]), "r"(b[1]));
}

#define CP16(dst, src) \
    asm volatile("cp.async.cg.shared.global [%0], [%1], 16;" \
                 :: "r"(dst), "l"(src) : "memory")
#define CPCOMMIT() asm volatile("cp.async.commit_group;" ::: "memory")
#define CPWAIT0()  asm volatile("cp.async.wait_group 0;" ::: "memory")

static __device__ __forceinline__ float fast_tanh(float x) {
    float e = __expf(2.f * x);
    return 1.f - __fdividef(2.f, e + 1.f);
}
static __device__ __forceinline__ float fast_sig(float x) {
    return __fdividef(1.f, 1.f + __expf(-x));
}

// =================== SCORES kernel (pipelined, full-N) =======================
// BM=128, BN=256, BK=32, 512 threads (16 warps 4x4), warp tile 32x64.
// SMEM: A stages @ 0 (2 x 20480: hi 10240 + lo 10240), B stages @ 40960
// (2 x 40960: hi 20480 + lo 20480). Row = 32 bf16 + 8 pad = 80 B.
#define SC_SA(s)  ((s) * 20480)
#define SC_SAL    10240
#define SC_SB(s)  (40960 + (s) * 40960)
#define SC_SBL    20480
#define SC_SMEM   122880

static __device__ __forceinline__ void sc_storeA(
    char* smem, uint32_t stage, uint32_t o0, uint32_t o1, float4 f0, float4 f1)
{
    const uint32_t base = SC_SA(stage);
#pragma unroll
    for (int q = 0; q < 2; q++) {
        float4 f = q ? f1 : f0;
        uint32_t off = q ? o1 : o0;
        __nv_bfloat16 h0 = __float2bfloat16(f.x);
        __nv_bfloat16 h1 = __float2bfloat16(f.y);
        __nv_bfloat16 h2 = __float2bfloat16(f.z);
        __nv_bfloat16 h3 = __float2bfloat16(f.w);
        __nv_bfloat16 l0 = __float2bfloat16(f.x - __bfloat162float(h0));
        __nv_bfloat16 l1 = __float2bfloat16(f.y - __bfloat162float(h1));
        __nv_bfloat16 l2 = __float2bfloat16(f.z - __bfloat162float(h2));
        __nv_bfloat16 l3 = __float2bfloat16(f.w - __bfloat162float(h3));
        uint2 uh, ul;
        uh.x = (uint32_t)__bfloat16_as_ushort(h0) |
               ((uint32_t)__bfloat16_as_ushort(h1) << 16);
        uh.y = (uint32_t)__bfloat16_as_ushort(h2) |
               ((uint32_t)__bfloat16_as_ushort(h3) << 16);
        ul.x = (uint32_t)__bfloat16_as_ushort(l0) |
               ((uint32_t)__bfloat16_as_ushort(l1) << 16);
        ul.y = (uint32_t)__bfloat16_as_ushort(l2) |
               ((uint32_t)__bfloat16_as_ushort(l3) << 16);
        *(uint2*)(smem + base + off) = uh;
        *(uint2*)(smem + base + SC_SAL + off) = ul;
    }
}

static __device__ __forceinline__ void sc_cpB(
    uint32_t sb, uint32_t stage, int k0, int bn, int bseg)
{
    uint32_t d = sb + SC_SB(stage);
    const __nv_bfloat16* sh = g_Wh + OW_SA;
    const __nv_bfloat16* sl = g_Wl + OW_SA;
    CP16(d + bn * 80 + bseg * 16,           sh + bn * 256 + k0 + bseg * 8);
    CP16(d + (bn + 128) * 80 + bseg * 16,   sh + (bn + 128) * 256 + k0 + bseg * 8);
    CP16(d + SC_SBL + bn * 80 + bseg * 16,  sl + bn * 256 + k0 + bseg * 8);
    CP16(d + SC_SBL + (bn + 128) * 80 + bseg * 16,
         sl + (bn + 128) * 256 + k0 + bseg * 8);
}

static __device__ __forceinline__ void sc_mma32(
    float (&acc)[2][8][4], uint32_t aA, uint32_t bB, uint32_t akb, uint32_t bkb)
{
#pragma unroll
    for (int kk = 0; kk < 2; kk++) {
        uint32_t ah[2][4], al[2][4];
        uint32_t aoff = (kk * 16 + akb) * 2;
        ldsm4(ah[0], aA + aoff);
        ldsm4(ah[1], aA + 1280 + aoff);
        ldsm4(al[0], aA + SC_SAL + aoff);
        ldsm4(al[1], aA + SC_SAL + 1280 + aoff);
        uint32_t boff = (kk * 16 + bkb) * 2;
#pragma unroll
        for (int g = 0; g < 4; g++) {
            uint32_t tb[4], tl[4];
            ldsm4(tb, bB + g * 1280 + boff);
            ldsm4(tl, bB + SC_SBL + g * 1280 + boff);
            uint32_t b0h[2] = {tb[0], tb[1]}, b1h[2] = {tb[2], tb[3]};
            uint32_t b0l[2] = {tl[0], tl[1]}, b1l[2] = {tl[2], tl[3]};
#pragma unroll
            for (int mi = 0; mi < 2; mi++) {
                mma_bf16(acc[mi][2 * g],     ah[mi], b0h);
                mma_bf16(acc[mi][2 * g],     al[mi], b0h);
                mma_bf16(acc[mi][2 * g],     ah[mi], b0l);
                mma_bf16(acc[mi][2 * g + 1], ah[mi], b1h);
                mma_bf16(acc[mi][2 * g + 1], al[mi], b1h);
                mma_bf16(acc[mi][2 * g + 1], ah[mi], b1l);
            }
        }
    }
}

__global__ void __launch_bounds__(512, 1)
attn_scores_tc2(const float* __restrict__ S, const float* __restrict__ hb,
                const float* __restrict__ va, float* __restrict__ scores)
{
    extern __shared__ char smem[];
    const uint32_t sb = smem_u32(smem);
    const int tid = threadIdx.x, lane = tid & 31, wid = tid >> 5;
    const int warpM = wid >> 2, warpN = wid & 3;
    const int row0 = blockIdx.x * 128;

    float acc[2][8][4];
#pragma unroll
    for (int a = 0; a < 2; a++)
#pragma unroll
        for (int b = 0; b < 8; b++)
#pragma unroll
            for (int c = 0; c < 4; c++) acc[a][b][c] = 0.f;

    const uint32_t arow = warpM * 32 + ((lane >> 3) & 1) * 8 + (lane & 7);
    const uint32_t akb  = ((lane >> 4) & 1) * 8;
    const uint32_t brow = warpN * 64 + ((lane >> 4) & 1) * 8 + (lane & 7);
    const uint32_t bkb  = ((lane >> 3) & 1) * 8;

    // A ldg mapping: idx = tid (+512) -> r = idx>>3, c4 = idx&7
    const int r0i = tid >> 3, c4 = tid & 7;
    const float* gA0 = S + (size_t)(row0 + r0i) * UU + c4 * 4;
    const float* gA1 = gA0 + (size_t)64 * UU;
    const uint32_t stA0 = r0i * 80 + c4 * 8;
    const uint32_t stA1 = stA0 + 64 * 80;
    // B cp.async mapping: idx = tid -> n = tid>>2, seg = tid&3 (plus n+128)
    const int bn = tid >> 2, bseg = tid & 3;

    // prologue: chunk 0
    float4 pf0 = *(const float4*)(gA0);
    float4 pf1 = *(const float4*)(gA1);
    sc_cpB(sb, 0, 0, bn, bseg);
    CPCOMMIT();
    sc_storeA(smem, 0, stA0, stA1, pf0, pf1);
    CPWAIT0();
    __syncthreads();

    for (int c = 0; c < 8; c++) {
        const int cur = c & 1, nxt = cur ^ 1;
        if (c < 7) {
            const int k0 = (c + 1) * 32;
            pf0 = *(const float4*)(gA0 + k0);
            pf1 = *(const float4*)(gA1 + k0);
            sc_cpB(sb, nxt, k0, bn, bseg);
            CPCOMMIT();
        }
        sc_mma32(acc, sb + SC_SA(cur) + arow * 80,
                 sb + SC_SB(cur) + brow * 80, akb, bkb);
        if (c < 7) {
            sc_storeA(smem, nxt, stA0, stA1, pf0, pf1);
            CPWAIT0();
        }
        __syncthreads();
    }

    // ---- epilogue: tanh + dot(v_a) reduce over full N=256 -------------------
    float* red = (float*)smem;                 // [128][4]
    float* sHB = (float*)(smem + 2048);        // [4][256]
    float* sVA = (float*)(smem + 6144);        // [256]
    const int b_first = row0 / MM;
    for (int i = tid; i < 1024; i += 512) {
        int j = i >> 8, cc = i & 255;
        int bb = b_first + j; if (bb > B_ - 1) bb = B_ - 1;
        sHB[i] = hb[(size_t)bb * UU + cc];
    }
    if (tid < 256) sVA[tid] = va[tid];
    __syncthreads();

#pragma unroll
    for (int mi = 0; mi < 2; mi++)
#pragma unroll
        for (int hf = 0; hf < 2; hf++) {
            const int rloc = warpM * 32 + mi * 16 + (lane >> 2) + hf * 8;
            const int bj = (row0 + rloc) / MM - b_first;
            const float* hrow = sHB + bj * 256;
            float p = 0.f;
#pragma unroll
            for (int ni = 0; ni < 8; ni++) {
                const int cc = warpN * 64 + ni * 8 + (lane & 3) * 2;
                p += fast_tanh(acc[mi][ni][hf * 2] + hrow[cc]) * sVA[cc];
                p += fast_tanh(acc[mi][ni][hf * 2 + 1] + hrow[cc + 1]) * sVA[cc + 1];
            }
            p += __shfl_xor_sync(0xffffffffu, p, 1);
            p += __shfl_xor_sync(0xffffffffu, p, 2);
            if ((lane & 3) == 0) red[rloc * 4 + warpN] = p;
        }
    __syncthreads();
    if (tid < 128)
        scores[row0 + tid] = red[tid * 4] + red[tid * 4 + 1] +
                             red[tid * 4 + 2] + red[tid * 4 + 3];
}

// =================== GATE kernels (round-3 machinery, y-fused) ===============
#define LDS_ROW 72
#define SA_H 0
#define SA_L 9216
#define SB_H 18432
#define SB_L 36864
#define SMEM_MMA 55296

static __device__ __forceinline__ void load_Atile(
    const float* __restrict__ A, int K, int row0, int k0, char* smem, int tid)
{
#pragma unroll
    for (int i = 0; i < 4; i++) {
        int idx = tid + (i << 8);
        int r = idx >> 4, c4 = idx & 15;
        float4 f = *(const float4*)(A + (size_t)(row0 + r) * K + k0 + (c4 << 2));
        __nv_bfloat16 h0 = __float2bfloat16(f.x);
        __nv_bfloat16 h1 = __float2bfloat16(f.y);
        __nv_bfloat16 h2 = __float2bfloat16(f.z);
        __nv_bfloat16 h3 = __float2bfloat16(f.w);
        __nv_bfloat16 l0 = __float2bfloat16(f.x - __bfloat162float(h0));
        __nv_bfloat16 l1 = __float2bfloat16(f.y - __bfloat162float(h1));
        __nv_bfloat16 l2 = __float2bfloat16(f.z - __bfloat162float(h2));
        __nv_bfloat16 l3 = __float2bfloat16(f.w - __bfloat162float(h3));
        uint2 uh, ul;
        uh.x = (uint32_t)__bfloat16_as_ushort(h0) |
               ((uint32_t)__bfloat16_as_ushort(h1) << 16);
        uh.y = (uint32_t)__bfloat16_as_ushort(h2) |
               ((uint32_t)__bfloat16_as_ushort(h3) << 16);
        ul.x = (uint32_t)__bfloat16_as_ushort(l0) |
               ((uint32_t)__bfloat16_as_ushort(l1) << 16);
        ul.y = (uint32_t)__bfloat16_as_ushort(l2) |
               ((uint32_t)__bfloat16_as_ushort(l3) << 16);
        uint32_t off = (uint32_t)(r * LDS_ROW + (c4 << 2)) * 2;
        *(uint2*)(smem + SA_H + off) = uh;
        *(uint2*)(smem + SA_L + off) = ul;
    }
}

static __device__ __forceinline__ void load_Btile(
    int woff, int K, int n0, int k0, char* smem, int tid)
{
    const __nv_bfloat16* Bh = g_Wh + woff;
    const __nv_bfloat16* Bl = g_Wl + woff;
#pragma unroll
    for (int i = 0; i < 8; i++) {
        int idx = tid + (i << 8);
        int r = idx >> 4, u = idx & 15;
        uint2 vh = *(const uint2*)(Bh + (size_t)(n0 + r) * K + k0 + (u << 2));
        uint2 vl = *(const uint2*)(Bl + (size_t)(n0 + r) * K + k0 + (u << 2));
        uint32_t off = (uint32_t)(r * LDS_ROW + (u << 2)) * 2;
        *(uint2*)(smem + SB_H + off) = vh;
        *(uint2*)(smem + SB_L + off) = vl;
    }
}

static __device__ __forceinline__ void mma_chunk(
    float (&acc)[2][4][4], uint32_t sb, int warpM, int warpN, int lane)
{
    const int arow = warpM * 32 + ((lane >> 3) & 1) * 8 + (lane & 7);
    const int brow = warpN * 32 + ((lane >> 4) & 1) * 8 + (lane & 7);
    const uint32_t akb = ((lane >> 4) & 1) * 8;
    const uint32_t bkb = ((lane >> 3) & 1) * 8;
    const uint32_t aBase = sb + (uint32_t)(arow * LDS_ROW) * 2;
    const uint32_t bBase = sb + (uint32_t)(brow * LDS_ROW) * 2;

#pragma unroll
    for (int kk = 0; kk < 4; kk++) {
        uint32_t ah[2][4], al[2][4];
        uint32_t aoff = (kk * 16 + akb) * 2;
        ldsm4(ah[0], aBase + SA_H + aoff);
        ldsm4(ah[1], aBase + SA_H + aoff + 16 * LDS_ROW * 2);
        ldsm4(al[0], aBase + SA_L + aoff);
        ldsm4(al[1], aBase + SA_L + aoff + 16 * LDS_ROW * 2);

        uint32_t boff = (kk * 16 + bkb) * 2;
        uint32_t t[4], u[4], tl[4], ul2[4];
        ldsm4(t,   bBase + SB_H + boff);
        ldsm4(u,   bBase + SB_H + boff + 16 * LDS_ROW * 2);
        ldsm4(tl,  bBase + SB_L + boff);
        ldsm4(ul2, bBase + SB_L + boff + 16 * LDS_ROW * 2);
        uint32_t bh[4][2] = {{t[0], t[1]}, {t[2], t[3]}, {u[0], u[1]}, {u[2], u[3]}};
        uint32_t bl[4][2] = {{tl[0], tl[1]}, {tl[2], tl[3]}, {ul2[0], ul2[1]}, {ul2[2], ul2[3]}};
#pragma unroll
        for (int ni = 0; ni < 4; ni++) {
#pragma unroll
            for (int mi = 0; mi < 2; mi++) {
                mma_bf16(acc[mi][ni], ah[mi], bh[ni]);
                mma_bf16(acc[mi][ni], al[mi], bh[ni]);
                mma_bf16(acc[mi][ni], ah[mi], bl[ni]);
            }
        }
    }
}

struct GateArgs {
    const float *text, *h, *X, *V;
    const float *ba, *bf, *bo, *bt, *bk, *bs, *bv;
    float *hb, *F, *O, *T;
};

__global__ void __launch_bounds__(256)
gate_mma(GateArgs g, int mode)
{
    extern __shared__ char smem[];
    const uint32_t sb = smem_u32(smem);
    const int tid = threadIdx.x, lane = tid & 31, wid = tid >> 5;
    const int warpM = wid >> 2, warpN = wid & 3;
    const int y = blockIdx.y;
    const int out = (mode == 0) ? 0 : (y >> 1);
    const int nh  = (mode == 0) ? y : (y & 1);
    const int row0 = blockIdx.x * 64;
    const int nloc0 = nh * 128;

    int region, Kfull, nglob0, cs = 0, ce;
    if (mode == 0)      { region = OW_HA;  Kfull = 256;  nglob0 = nloc0; ce = 4; }
    else if (mode == 1) { region = OW_FOT; Kfull = 512;  nglob0 = out * 256 + nloc0; ce = 8; }
    else                { region = OW_KHH; Kfull = 1024; nglob0 = out * 256 + nloc0;
                          ce = (out == 1) ? 12 : 16; cs = (out == 2) ? 8 : 0; }

    float acc[2][4][4];
#pragma unroll
    for (int a = 0; a < 2; a++)
#pragma unroll
        for (int b = 0; b < 4; b++)
#pragma unroll
            for (int c = 0; c < 4; c++) acc[a][b][c] = 0.f;

    for (int cc = cs; cc < ce; cc++) {
        const float* A; int KA, kloc;
        if (mode == 0)      { A = g.h; KA = 256; kloc = cc * 64; }
        else if (mode == 1) {
            if (cc < 4) { A = g.text; KA = 256; kloc = cc * 64; }
            else        { A = g.h;    KA = 256; kloc = (cc - 4) * 64; }
        } else {
            if (cc < 8)       { A = g.X; KA = 512; kloc = cc * 64; }
            else if (cc < 12) { A = g.h; KA = 256; kloc = (cc - 8) * 64; }
            else              { A = g.V; KA = 256; kloc = (cc - 12) * 64; }
        }
        load_Atile(A, KA, row0, kloc, smem, tid);
        load_Btile(region, Kfull, nglob0, cc * 64, smem, tid);
        __syncthreads();
        mma_chunk(acc, sb, warpM, warpN, lane);
        __syncthreads();
    }

    const float* bias; float* outp; int act;
    if (mode == 0)      { bias = g.ba; outp = g.hb; act = 0; }
    else if (mode == 1) {
        if (out == 0)      { bias = g.bf; outp = g.F; act = 1; }
        else if (out == 1) { bias = g.bo; outp = g.O; act = 1; }
        else               { bias = g.bt; outp = g.T; act = 2; }
    } else {
        if (out == 0)      { bias = g.bk; outp = g.F; act = 1; }
        else if (out == 1) { bias = g.bs; outp = g.O; act = 2; }
        else               { bias = g.bv; outp = g.T; act = 2; }
    }

#pragma unroll
    for (int mi = 0; mi < 2; mi++)
#pragma unroll
        for (int ni = 0; ni < 4; ni++) {
            int c = nloc0 + warpN * 32 + ni * 8 + (lane & 3) * 2;
            float b0 = bias[c], b1 = bias[c + 1];
            int r = row0 + warpM * 32 + mi * 16 + (lane >> 2);
#pragma unroll
            for (int hf = 0; hf < 2; hf++) {
                float x0 = acc[mi][ni][hf * 2 + 0] + b0;
                float x1 = acc[mi][ni][hf * 2 + 1] + b1;
                if (act == 1)      { x0 = fast_sig(x0);  x1 = fast_sig(x1); }
                else if (act == 2) { x0 = fast_tanh(x0); x1 = fast_tanh(x1); }
                *(float2*)(outp + (size_t)(r + hf * 8) * UU + c) =
                    make_float2(x0, x1);
            }
        }
}

// ---------------- weight prep -------------------------------------------------
struct WPtrs { const float* p[15]; };
// p: 0 W_sa, 1 W_ha, 2 W_f, 3 W_o, 4 W_t, 5 W_hf, 6 W_ho, 7 W_ht,
//    8 W_k, 9 W_s, 10 W_hk, 11 W_hs, 12 W_hv, 13 W_vk, 14 W_v

__global__ void __launch_bounds__(256)
wprep_all(WPtrs w)
{
    int idx = blockIdx.x * 256 + threadIdx.x;
    float x;
    if (idx < 65536) {
        int n = idx >> 8, kk = idx & 255;
        x = w.p[0][kk * 256 + n];
    } else if (idx < 131072) {
        int l = idx - 65536; int n = l >> 8, kk = l & 255;
        x = w.p[1][kk * 256 + n];
    } else if (idx < 524288) {
        int l = idx - 131072; int n = l >> 9, kk = l & 511;
        int out = n >> 8, nl = n & 255;
        const float* Wa = (out == 0) ? w.p[2] : (out == 1) ? w.p[3] : w.p[4];
        const float* Wb = (out == 0) ? w.p[5] : (out == 1) ? w.p[6] : w.p[7];
        x = (kk < 256) ? Wa[kk * 256 + nl] : Wb[(kk - 256) * 256 + nl];
    } else {
        int l = idx - 524288; int n = l >> 10, kk = l & 1023;
        int out = n >> 8, nl = n & 255;
        if (out == 0)
            x = (kk < 512) ? w.p[8][kk * 256 + nl]
              : (kk < 768) ? w.p[10][(kk - 512) * 256 + nl]
                           : w.p[13][(kk - 768) * 256 + nl];
        else if (out == 1)
            x = (kk < 512) ? w.p[9][kk * 256 + nl]
              : (kk < 768) ? w.p[11][(kk - 512) * 256 + nl] : 0.f;
        else
            x = (kk < 512) ? 0.f
              : (kk < 768) ? w.p[12][(kk - 512) * 256 + nl]
                           : w.p[14][(kk - 768) * 256 + nl];
    }
    __nv_bfloat16 h = __float2bfloat16(x);
    g_Wh[idx] = h;
    g_Wl[idx] = __float2bfloat16(x - __bfloat162float(h));
}

// --------------- fused softmax + text = P . S --------------------------------
__global__ void __launch_bounds__(256)
text_softmax(const float* __restrict__ S, const float* __restrict__ sc,
             float* __restrict__ P, float* __restrict__ text)
{
    const int b = blockIdx.x, tid = threadIdx.x;
    __shared__ float sp[MM];

    if (tid < 32) {
        float s0 = sc[b * MM + tid];
        float s1 = (tid < 18) ? sc[b * MM + tid + 32] : -1e30f;
        float mx = fmaxf(s0, s1);
#pragma unroll
        for (int off = 16; off > 0; off >>= 1)
            mx = fmaxf(mx, __shfl_xor_sync(0xffffffffu, mx, off));
        float e0 = expf(s0 - mx);
        float e1 = (tid < 18) ? expf(s1 - mx) : 0.f;
        float sum = e0 + e1;
#pragma unroll
        for (int off = 16; off > 0; off >>= 1)
            sum += __shfl_xor_sync(0xffffffffu, sum, off);
        float inv = 1.f / sum;
        sp[tid] = e0 * inv;
        P[b * MM + tid] = e0 * inv;
        if (tid < 18) { sp[tid + 32] = e1 * inv; P[b * MM + tid + 32] = e1 * inv; }
    }
    __syncthreads();

    const float* Sb = S + (size_t)b * MM * UU;
    float a = 0.f;
#pragma unroll 5
    for (int m = 0; m < MM; m++)
        a = fmaf(sp[m], Sb[m * UU + tid], a);
    text[(size_t)b * UU + tid] = a;
}

// ---------------- elementwise combines ---------------------------------------
__global__ void __launch_bounds__(256)
vcomb_kernel(const float* __restrict__ F, const float* __restrict__ O,
             const float* __restrict__ T, const float* __restrict__ v,
             float* __restrict__ V)
{
    int i = blockIdx.x * 256 + threadIdx.x;
    V[i] = fmaf(F[i], v[i], O[i] * T[i]);
}

__global__ void __launch_bounds__(256)
hcomb_kernel(const float* __restrict__ k, const float* __restrict__ hv,
             const float* __restrict__ hx, float* __restrict__ H)
{
    int i = blockIdx.x * 256 + threadIdx.x;
    float kk = k[i];
    H[i] = fmaf(1.f - kk, hv[i], kk * hx[i]);
}

// ---------------- launch ------------------------------------------------------
extern "C" void kernel_launch(void* const* d_in, const int* in_sizes, int n_in,
                              void* d_out, int out_size)
{
    const float* X    = (const float*)d_in[0];
    const float* S    = (const float*)d_in[1];
    const float* h    = (const float*)d_in[2];
    const float* v    = (const float*)d_in[3];
    const float* W_sa = (const float*)d_in[4];
    const float* W_ha = (const float*)d_in[5];
    const float* b_a  = (const float*)d_in[6];
    const float* v_a  = (const float*)d_in[7];
    const float* W_f  = (const float*)d_in[8];
    const float* W_hf = (const float*)d_in[9];
    const float* b_f  = (const float*)d_in[10];
    const float* W_o  = (const float*)d_in[11];
    const float* W_ho = (const float*)d_in[12];
    const float* b_o  = (const float*)d_in[13];
    const float* W_t  = (const float*)d_in[14];
    const float* W_ht = (const float*)d_in[15];
    const float* b_t  = (const float*)d_in[16];
    const float* W_k  = (const float*)d_in[17];
    const float* W_hk = (const float*)d_in[18];
    const float* W_vk = (const float*)d_in[19];
    const float* b_k  = (const float*)d_in[20];
    const float* W_s  = (const float*)d_in[21];
    const float* W_hs = (const float*)d_in[22];
    const float* b_s  = (const float*)d_in[23];
    const float* W_v  = (const float*)d_in[24];
    const float* W_hv = (const float*)d_in[25];
    const float* b_v  = (const float*)d_in[26];

    float* outH = (float*)d_out;
    float* outP = outH + (size_t)B_ * UU;
    float* outV = outP + (size_t)B_ * MM;

    float *hb, *scores, *text, *Fb, *Ob, *Tb;
    cudaGetSymbolAddress((void**)&hb,     g_hb);
    cudaGetSymbolAddress((void**)&scores, g_scores);
    cudaGetSymbolAddress((void**)&text,   g_text);
    cudaGetSymbolAddress((void**)&Fb,     g_F);
    cudaGetSymbolAddress((void**)&Ob,     g_O);
    cudaGetSymbolAddress((void**)&Tb,     g_T);

    cudaFuncSetAttribute(attn_scores_tc2,
                         cudaFuncAttributeMaxDynamicSharedMemorySize, SC_SMEM);
    cudaFuncSetAttribute(gate_mma,
                         cudaFuncAttributeMaxDynamicSharedMemorySize, SMEM_MMA);

    // 0. weight prep into regions
    WPtrs wp;
    wp.p[0] = W_sa; wp.p[1] = W_ha; wp.p[2] = W_f;  wp.p[3] = W_o;
    wp.p[4] = W_t;  wp.p[5] = W_hf; wp.p[6] = W_ho; wp.p[7] = W_ht;
    wp.p[8] = W_k;  wp.p[9] = W_s;  wp.p[10] = W_hk; wp.p[11] = W_hs;
    wp.p[12] = W_hv; wp.p[13] = W_vk; wp.p[14] = W_v;
    wprep_all<<<WTOT / 256, 256>>>(wp);

    GateArgs ga;
    ga.text = text; ga.h = h; ga.X = X; ga.V = outV;
    ga.ba = b_a; ga.bf = b_f; ga.bo = b_o; ga.bt = b_t;
    ga.bk = b_k; ga.bs = b_s; ga.bv = b_v;
    ga.hb = hb; ga.F = Fb; ga.O = Ob; ga.T = Tb;

    const int ewBlocks = (B_ * UU) / 256;

    // 1. hb = h @ W_ha + b_a
    gate_mma<<<dim3(B_ / 64, 2), 256, SMEM_MMA>>>(ga, 0);
    // 2. scores (pipelined tcgen-less HMMA, fused tanh + dot v_a)
    attn_scores_tc2<<<BMROWS / 128, 512, SC_SMEM>>>(S, hb, v_a, scores);
    // 3. P = softmax(scores); text = P . S   (fused)
    text_softmax<<<B_, 256>>>(S, scores, outP, text);
    // 4. F, O, T in one launch
    gate_mma<<<dim3(B_ / 64, 6), 256, SMEM_MMA>>>(ga, 1);
    // 5. V = F*v + O*text_new
    vcomb_kernel<<<ewBlocks, 256>>>(Fb, Ob, Tb, v, outV);
    // 6. k, hx, hv in one launch (k->Fb, hx->Ob, hv->Tb)
    gate_mma<<<dim3(B_ / 64, 6), 256, SMEM_MMA>>>(ga, 2);
    // 7. H = (1-k)*hv + k*hx
    hcomb_kernel<<<ewBlocks, 256>>>(Fb, Tb, Ob, outH);
}

// round 8
// speedup vs baseline: 1.0006x; 1.0006x over previous
#include <cuda_runtime.h>
#include <cuda_bf16.h>
#include <math.h>
#include <cstdint>

// Problem constants
#define B_     8192
#define DIN    512
#define UU     256
#define MM     50
#define BMROWS (B_ * MM)     // 409600

// ---------------- scratch (device globals; no allocation allowed) ----------
__device__ float g_hb[B_ * UU];
__device__ float g_scores[BMROWS];
__device__ float g_text[B_ * UU];
__device__ float g_F[B_ * UU];
__device__ float g_O[B_ * UU];
__device__ float g_T[B_ * UU];

// prepped weights, bf16 hi/lo, [N][K] row-major regions:
//   OW_SA  [256][256]   W_sa^T
//   OW_HA  [256][256]   W_ha^T
//   OW_FOT [768][512]   n: F|O|T,  k: text(256)|h(256)
//   OW_KHH [768][1024]  n: k|hx|hv, k: X(512)|h(256)|V(256)
#define OW_SA  0
#define OW_HA  65536
#define OW_FOT 131072
#define OW_KHH 524288
#define WTOT   1310720
__device__ __nv_bfloat16 g_Wh[WTOT];
__device__ __nv_bfloat16 g_Wl[WTOT];

// ======================= low-level helpers ==================================
static __device__ __forceinline__ uint32_t smem_u32(const void* p) {
    uint32_t a;
    asm("{ .reg .u64 t; cvta.to.shared.u64 t, %1; cvt.u32.u64 %0, t; }"
        : "=r"(a) : "l"(p));
    return a;
}

static __device__ __forceinline__ void ldsm4(uint32_t* r, uint32_t a) {
    asm volatile("ldmatrix.sync.aligned.m8n8.x4.shared.b16 {%0,%1,%2,%3}, [%4];"
                 : "=r"(r[0]), "=r"(r[1]), "=r"(r[2]), "=r"(r[3]) : "r"(a));
}

static __device__ __forceinline__ void mma_bf16(float* c, const uint32_t* a,
                                                const uint32_t* b) {
    asm volatile(
        "mma.sync.aligned.m16n8k16.row.col.f32.bf16.bf16.f32 "
        "{%0,%1,%2,%3}, {%4,%5,%6,%7}, {%8,%9}, {%0,%1,%2,%3};"
        : "+f"(c[0]), "+f"(c[1]), "+f"(c[2]), "+f"(c[3])
        : "r"(a[0]), "r"(a[1]), "r"(a[2]), "r"(a[3]), "r"(b[0]), "r"(b[1]));
}

#define CP16(dst, src) \
    asm volatile("cp.async.cg.shared.global [%0], [%1], 16;" \
                 :: "r"(dst), "l"(src) : "memory")
#define CPCOMMIT() asm volatile("cp.async.commit_group;" ::: "memory")
#define CPWAIT0()  asm volatile("cp.async.wait_group 0;" ::: "memory")

static __device__ __forceinline__ float fast_tanh(float x) {
    float e = __expf(2.f * x);
    return 1.f - __fdividef(2.f, e + 1.f);
}
static __device__ __forceinline__ float fast_sig(float x) {
    return __fdividef(1.f, 1.f + __expf(-x));
}

// =================== SCORES kernel (pipelined, full-N) =======================
// BM=128, BN=256, BK=32, 512 threads (16 warps 4x4), warp tile 32x64.
// SMEM: A stages @ 0 (2 x 20480: hi 10240 + lo 10240), B stages @ 40960
// (2 x 40960: hi 20480 + lo 20480). Row = 32 bf16 + 8 pad = 80 B.
#define SC_SA(s)  ((s) * 20480)
#define SC_SAL    10240
#define SC_SB(s)  (40960 + (s) * 40960)
#define SC_SBL    20480
#define SC_SMEM   122880

static __device__ __forceinline__ void sc_storeA(
    char* smem, uint32_t stage, uint32_t o0, uint32_t o1, float4 f0, float4 f1)
{
    const uint32_t base = SC_SA(stage);
#pragma unroll
    for (int q = 0; q < 2; q++) {
        float4 f = q ? f1 : f0;
        uint32_t off = q ? o1 : o0;
        __nv_bfloat16 h0 = __float2bfloat16(f.x);
        __nv_bfloat16 h1 = __float2bfloat16(f.y);
        __nv_bfloat16 h2 = __float2bfloat16(f.z);
        __nv_bfloat16 h3 = __float2bfloat16(f.w);
        __nv_bfloat16 l0 = __float2bfloat16(f.x - __bfloat162float(h0));
        __nv_bfloat16 l1 = __float2bfloat16(f.y - __bfloat162float(h1));
        __nv_bfloat16 l2 = __float2bfloat16(f.z - __bfloat162float(h2));
        __nv_bfloat16 l3 = __float2bfloat16(f.w - __bfloat162float(h3));
        uint2 uh, ul;
        uh.x = (uint32_t)__bfloat16_as_ushort(h0) |
               ((uint32_t)__bfloat16_as_ushort(h1) << 16);
        uh.y = (uint32_t)__bfloat16_as_ushort(h2) |
               ((uint32_t)__bfloat16_as_ushort(h3) << 16);
        ul.x = (uint32_t)__bfloat16_as_ushort(l0) |
               ((uint32_t)__bfloat16_as_ushort(l1) << 16);
        ul.y = (uint32_t)__bfloat16_as_ushort(l2) |
               ((uint32_t)__bfloat16_as_ushort(l3) << 16);
        *(uint2*)(smem + base + off) = uh;
        *(uint2*)(smem + base + SC_SAL + off) = ul;
    }
}

static __device__ __forceinline__ void sc_cpB(
    uint32_t sb, uint32_t stage, int k0, int bn, int bseg)
{
    uint32_t d = sb + SC_SB(stage);
    const __nv_bfloat16* sh = g_Wh + OW_SA;
    const __nv_bfloat16* sl = g_Wl + OW_SA;
    CP16(d + bn * 80 + bseg * 16,           sh + bn * 256 + k0 + bseg * 8);
    CP16(d + (bn + 128) * 80 + bseg * 16,   sh + (bn + 128) * 256 + k0 + bseg * 8);
    CP16(d + SC_SBL + bn * 80 + bseg * 16,  sl + bn * 256 + k0 + bseg * 8);
    CP16(d + SC_SBL + (bn + 128) * 80 + bseg * 16,
         sl + (bn + 128) * 256 + k0 + bseg * 8);
}

static __device__ __forceinline__ void sc_mma32(
    float (&acc)[2][8][4], uint32_t aA, uint32_t bB, uint32_t akb, uint32_t bkb)
{
#pragma unroll
    for (int kk = 0; kk < 2; kk++) {
        uint32_t ah[2][4], al[2][4];
        uint32_t aoff = (kk * 16 + akb) * 2;
        ldsm4(ah[0], aA + aoff);
        ldsm4(ah[1], aA + 1280 + aoff);
        ldsm4(al[0], aA + SC_SAL + aoff);
        ldsm4(al[1], aA + SC_SAL + 1280 + aoff);
        uint32_t boff = (kk * 16 + bkb) * 2;
#pragma unroll
        for (int g = 0; g < 4; g++) {
            uint32_t tb[4], tl[4];
            ldsm4(tb, bB + g * 1280 + boff);
            ldsm4(tl, bB + SC_SBL + g * 1280 + boff);
            uint32_t b0h[2] = {tb[0], tb[1]}, b1h[2] = {tb[2], tb[3]};
            uint32_t b0l[2] = {tl[0], tl[1]}, b1l[2] = {tl[2], tl[3]};
#pragma unroll
            for (int mi = 0; mi < 2; mi++) {
                mma_bf16(acc[mi][2 * g],     ah[mi], b0h);
                mma_bf16(acc[mi][2 * g],     al[mi], b0h);
                mma_bf16(acc[mi][2 * g],     ah[mi], b0l);
                mma_bf16(acc[mi][2 * g + 1], ah[mi], b1h);
                mma_bf16(acc[mi][2 * g + 1], al[mi], b1h);
                mma_bf16(acc[mi][2 * g + 1], ah[mi], b1l);
            }
        }
    }
}

__global__ void __launch_bounds__(512, 1)
attn_scores_tc2(const float* __restrict__ S, const float* __restrict__ hb,
                const float* __restrict__ va, float* __restrict__ scores)
{
    extern __shared__ char smem[];
    const uint32_t sb = smem_u32(smem);
    const int tid = threadIdx.x, lane = tid & 31, wid = tid >> 5;
    const int warpM = wid >> 2, warpN = wid & 3;
    const int row0 = blockIdx.x * 128;

    float acc[2][8][4];
#pragma unroll
    for (int a = 0; a < 2; a++)
#pragma unroll
        for (int b = 0; b < 8; b++)
#pragma unroll
            for (int c = 0; c < 4; c++) acc[a][b][c] = 0.f;

    const uint32_t arow = warpM * 32 + ((lane >> 3) & 1) * 8 + (lane & 7);
    const uint32_t akb  = ((lane >> 4) & 1) * 8;
    const uint32_t brow = warpN * 64 + ((lane >> 4) & 1) * 8 + (lane & 7);
    const uint32_t bkb  = ((lane >> 3) & 1) * 8;

    // A ldg mapping: idx = tid (+512) -> r = idx>>3, c4 = idx&7
    const int r0i = tid >> 3, c4 = tid & 7;
    const float* gA0 = S + (size_t)(row0 + r0i) * UU + c4 * 4;
    const float* gA1 = gA0 + (size_t)64 * UU;
    const uint32_t stA0 = r0i * 80 + c4 * 8;
    const uint32_t stA1 = stA0 + 64 * 80;
    // B cp.async mapping: idx = tid -> n = tid>>2, seg = tid&3 (plus n+128)
    const int bn = tid >> 2, bseg = tid & 3;

    // prologue: chunk 0
    float4 pf0 = *(const float4*)(gA0);
    float4 pf1 = *(const float4*)(gA1);
    sc_cpB(sb, 0, 0, bn, bseg);
    CPCOMMIT();
    sc_storeA(smem, 0, stA0, stA1, pf0, pf1);
    CPWAIT0();
    __syncthreads();

    for (int c = 0; c < 8; c++) {
        const int cur = c & 1, nxt = cur ^ 1;
        if (c < 7) {
            const int k0 = (c + 1) * 32;
            pf0 = *(const float4*)(gA0 + k0);
            pf1 = *(const float4*)(gA1 + k0);
            sc_cpB(sb, nxt, k0, bn, bseg);
            CPCOMMIT();
        }
        sc_mma32(acc, sb + SC_SA(cur) + arow * 80,
                 sb + SC_SB(cur) + brow * 80, akb, bkb);
        if (c < 7) {
            sc_storeA(smem, nxt, stA0, stA1, pf0, pf1);
            CPWAIT0();
        }
        __syncthreads();
    }

    // ---- epilogue: tanh + dot(v_a) reduce over full N=256 -------------------
    float* red = (float*)smem;                 // [128][4]
    float* sHB = (float*)(smem + 2048);        // [4][256]
    float* sVA = (float*)(smem + 6144);        // [256]
    const int b_first = row0 / MM;
    for (int i = tid; i < 1024; i += 512) {
        int j = i >> 8, cc = i & 255;
        int bb = b_first + j; if (bb > B_ - 1) bb = B_ - 1;
        sHB[i] = hb[(size_t)bb * UU + cc];
    }
    if (tid < 256) sVA[tid] = va[tid];
    __syncthreads();

#pragma unroll
    for (int mi = 0; mi < 2; mi++)
#pragma unroll
        for (int hf = 0; hf < 2; hf++) {
            const int rloc = warpM * 32 + mi * 16 + (lane >> 2) + hf * 8;
            const int bj = (row0 + rloc) / MM - b_first;
            const float* hrow = sHB + bj * 256;
            float p = 0.f;
#pragma unroll
            for (int ni = 0; ni < 8; ni++) {
                const int cc = warpN * 64 + ni * 8 + (lane & 3) * 2;
                p += fast_tanh(acc[mi][ni][hf * 2] + hrow[cc]) * sVA[cc];
                p += fast_tanh(acc[mi][ni][hf * 2 + 1] + hrow[cc + 1]) * sVA[cc + 1];
            }
            p += __shfl_xor_sync(0xffffffffu, p, 1);
            p += __shfl_xor_sync(0xffffffffu, p, 2);
            if ((lane & 3) == 0) red[rloc * 4 + warpN] = p;
        }
    __syncthreads();
    if (tid < 128)
        scores[row0 + tid] = red[tid * 4] + red[tid * 4 + 1] +
                             red[tid * 4 + 2] + red[tid * 4 + 3];
}

// =================== GATE kernels (round-3 machinery, y-fused) ===============
#define LDS_ROW 72
#define SA_H 0
#define SA_L 9216
#define SB_H 18432
#define SB_L 36864
#define SMEM_MMA 55296

static __device__ __forceinline__ void load_Atile(
    const float* __restrict__ A, int K, int row0, int k0, char* smem, int tid)
{
#pragma unroll
    for (int i = 0; i < 4; i++) {
        int idx = tid + (i << 8);
        int r = idx >> 4, c4 = idx & 15;
        float4 f = *(const float4*)(A + (size_t)(row0 + r) * K + k0 + (c4 << 2));
        __nv_bfloat16 h0 = __float2bfloat16(f.x);
        __nv_bfloat16 h1 = __float2bfloat16(f.y);
        __nv_bfloat16 h2 = __float2bfloat16(f.z);
        __nv_bfloat16 h3 = __float2bfloat16(f.w);
        __nv_bfloat16 l0 = __float2bfloat16(f.x - __bfloat162float(h0));
        __nv_bfloat16 l1 = __float2bfloat16(f.y - __bfloat162float(h1));
        __nv_bfloat16 l2 = __float2bfloat16(f.z - __bfloat162float(h2));
        __nv_bfloat16 l3 = __float2bfloat16(f.w - __bfloat162float(h3));
        uint2 uh, ul;
        uh.x = (uint32_t)__bfloat16_as_ushort(h0) |
               ((uint32_t)__bfloat16_as_ushort(h1) << 16);
        uh.y = (uint32_t)__bfloat16_as_ushort(h2) |
               ((uint32_t)__bfloat16_as_ushort(h3) << 16);
        ul.x = (uint32_t)__bfloat16_as_ushort(l0) |
               ((uint32_t)__bfloat16_as_ushort(l1) << 16);
        ul.y = (uint32_t)__bfloat16_as_ushort(l2) |
               ((uint32_t)__bfloat16_as_ushort(l3) << 16);
        uint32_t off = (uint32_t)(r * LDS_ROW + (c4 << 2)) * 2;
        *(uint2*)(smem + SA_H + off) = uh;
        *(uint2*)(smem + SA_L + off) = ul;
    }
}

static __device__ __forceinline__ void load_Btile(
    int woff, int K, int n0, int k0, char* smem, int tid)
{
    const __nv_bfloat16* Bh = g_Wh + woff;
    const __nv_bfloat16* Bl = g_Wl + woff;
#pragma unroll
    for (int i = 0; i < 8; i++) {
        int idx = tid + (i << 8);
        int r = idx >> 4, u = idx & 15;
        uint2 vh = *(const uint2*)(Bh + (size_t)(n0 + r) * K + k0 + (u << 2));
        uint2 vl = *(const uint2*)(Bl + (size_t)(n0 + r) * K + k0 + (u << 2));
        uint32_t off = (uint32_t)(r * LDS_ROW + (u << 2)) * 2;
        *(uint2*)(smem + SB_H + off) = vh;
        *(uint2*)(smem + SB_L + off) = vl;
    }
}

static __device__ __forceinline__ void mma_chunk(
    float (&acc)[2][4][4], uint32_t sb, int warpM, int warpN, int lane)
{
    const int arow = warpM * 32 + ((lane >> 3) & 1) * 8 + (lane & 7);
    const int brow = warpN * 32 + ((lane >> 4) & 1) * 8 + (lane & 7);
    const uint32_t akb = ((lane >> 4) & 1) * 8;
    const uint32_t bkb = ((lane >> 3) & 1) * 8;
    const uint32_t aBase = sb + (uint32_t)(arow * LDS_ROW) * 2;
    const uint32_t bBase = sb + (uint32_t)(brow * LDS_ROW) * 2;

#pragma unroll
    for (int kk = 0; kk < 4; kk++) {
        uint32_t ah[2][4], al[2][4];
        uint32_t aoff = (kk * 16 + akb) * 2;
        ldsm4(ah[0], aBase + SA_H + aoff);
        ldsm4(ah[1], aBase + SA_H + aoff + 16 * LDS_ROW * 2);
        ldsm4(al[0], aBase + SA_L + aoff);
        ldsm4(al[1], aBase + SA_L + aoff + 16 * LDS_ROW * 2);

        uint32_t boff = (kk * 16 + bkb) * 2;
        uint32_t t[4], u[4], tl[4], ul2[4];
        ldsm4(t,   bBase + SB_H + boff);
        ldsm4(u,   bBase + SB_H + boff + 16 * LDS_ROW * 2);
        ldsm4(tl,  bBase + SB_L + boff);
        ldsm4(ul2, bBase + SB_L + boff + 16 * LDS_ROW * 2);
        uint32_t bh[4][2] = {{t[0], t[1]}, {t[2], t[3]}, {u[0], u[1]}, {u[2], u[3]}};
        uint32_t bl[4][2] = {{tl[0], tl[1]}, {tl[2], tl[3]}, {ul2[0], ul2[1]}, {ul2[2], ul2[3]}};
#pragma unroll
        for (int ni = 0; ni < 4; ni++) {
#pragma unroll
            for (int mi = 0; mi < 2; mi++) {
                mma_bf16(acc[mi][ni], ah[mi], bh[ni]);
                mma_bf16(acc[mi][ni], al[mi], bh[ni]);
                mma_bf16(acc[mi][ni], ah[mi], bl[ni]);
            }
        }
    }
}

struct GateArgs {
    const float *text, *h, *X, *V;
    const float *ba, *bf, *bo, *bt, *bk, *bs, *bv;
    float *hb, *F, *O, *T;
};

__global__ void __launch_bounds__(256)
gate_mma(GateArgs g, int mode)
{
    extern __shared__ char smem[];
    const uint32_t sb = smem_u32(smem);
    const int tid = threadIdx.x, lane = tid & 31, wid = tid >> 5;
    const int warpM = wid >> 2, warpN = wid & 3;
    const int y = blockIdx.y;
    const int out = (mode == 0) ? 0 : (y >> 1);
    const int nh  = (mode == 0) ? y : (y & 1);
    const int row0 = blockIdx.x * 64;
    const int nloc0 = nh * 128;

    int region, Kfull, nglob0, cs = 0, ce;
    if (mode == 0)      { region = OW_HA;  Kfull = 256;  nglob0 = nloc0; ce = 4; }
    else if (mode == 1) { region = OW_FOT; Kfull = 512;  nglob0 = out * 256 + nloc0; ce = 8; }
    else                { region = OW_KHH; Kfull = 1024; nglob0 = out * 256 + nloc0;
                          ce = (out == 1) ? 12 : 16; cs = (out == 2) ? 8 : 0; }

    float acc[2][4][4];
#pragma unroll
    for (int a = 0; a < 2; a++)
#pragma unroll
        for (int b = 0; b < 4; b++)
#pragma unroll
            for (int c = 0; c < 4; c++) acc[a][b][c] = 0.f;

    for (int cc = cs; cc < ce; cc++) {
        const float* A; int KA, kloc;
        if (mode == 0)      { A = g.h; KA = 256; kloc = cc * 64; }
        else if (mode == 1) {
            if (cc < 4) { A = g.text; KA = 256; kloc = cc * 64; }
            else        { A = g.h;    KA = 256; kloc = (cc - 4) * 64; }
        } else {
            if (cc < 8)       { A = g.X; KA = 512; kloc = cc * 64; }
            else if (cc < 12) { A = g.h; KA = 256; kloc = (cc - 8) * 64; }
            else              { A = g.V; KA = 256; kloc = (cc - 12) * 64; }
        }
        load_Atile(A, KA, row0, kloc, smem, tid);
        load_Btile(region, Kfull, nglob0, cc * 64, smem, tid);
        __syncthreads();
        mma_chunk(acc, sb, warpM, warpN, lane);
        __syncthreads();
    }

    const float* bias; float* outp; int act;
    if (mode == 0)      { bias = g.ba; outp = g.hb; act = 0; }
    else if (mode == 1) {
        if (out == 0)      { bias = g.bf; outp = g.F; act = 1; }
        else if (out == 1) { bias = g.bo; outp = g.O; act = 1; }
        else               { bias = g.bt; outp = g.T; act = 2; }
    } else {
        if (out == 0)      { bias = g.bk; outp = g.F; act = 1; }
        else if (out == 1) { bias = g.bs; outp = g.O; act = 2; }
        else               { bias = g.bv; outp = g.T; act = 2; }
    }

#pragma unroll
    for (int mi = 0; mi < 2; mi++)
#pragma unroll
        for (int ni = 0; ni < 4; ni++) {
            int c = nloc0 + warpN * 32 + ni * 8 + (lane & 3) * 2;
            float b0 = bias[c], b1 = bias[c + 1];
            int r = row0 + warpM * 32 + mi * 16 + (lane >> 2);
#pragma unroll
            for (int hf = 0; hf < 2; hf++) {
                float x0 = acc[mi][ni][hf * 2 + 0] + b0;
                float x1 = acc[mi][ni][hf * 2 + 1] + b1;
                if (act == 1)      { x0 = fast_sig(x0);  x1 = fast_sig(x1); }
                else if (act == 2) { x0 = fast_tanh(x0); x1 = fast_tanh(x1); }
                *(float2*)(outp + (size_t)(r + hf * 8) * UU + c) =
                    make_float2(x0, x1);
            }
        }
}

// ---------------- weight prep -------------------------------------------------
struct WPtrs { const float* p[15]; };
// p: 0 W_sa, 1 W_ha, 2 W_f, 3 W_o, 4 W_t, 5 W_hf, 6 W_ho, 7 W_ht,
//    8 W_k, 9 W_s, 10 W_hk, 11 W_hs, 12 W_hv, 13 W_vk, 14 W_v

__global__ void __launch_bounds__(256)
wprep_all(WPtrs w)
{
    int idx = blockIdx.x * 256 + threadIdx.x;
    float x;
    if (idx < 65536) {
        int n = idx >> 8, kk = idx & 255;
        x = w.p[0][kk * 256 + n];
    } else if (idx < 131072) {
        int l = idx - 65536; int n = l >> 8, kk = l & 255;
        x = w.p[1][kk * 256 + n];
    } else if (idx < 524288) {
        int l = idx - 131072; int n = l >> 9, kk = l & 511;
        int out = n >> 8, nl = n & 255;
        const float* Wa = (out == 0) ? w.p[2] : (out == 1) ? w.p[3] : w.p[4];
        const float* Wb = (out == 0) ? w.p[5] : (out == 1) ? w.p[6] : w.p[7];
        x = (kk < 256) ? Wa[kk * 256 + nl] : Wb[(kk - 256) * 256 + nl];
    } else {
        int l = idx - 524288; int n = l >> 10, kk = l & 1023;
        int out = n >> 8, nl = n & 255;
        if (out == 0)
            x = (kk < 512) ? w.p[8][kk * 256 + nl]
              : (kk < 768) ? w.p[10][(kk - 512) * 256 + nl]
                           : w.p[13][(kk - 768) * 256 + nl];
        else if (out == 1)
            x = (kk < 512) ? w.p[9][kk * 256 + nl]
              : (kk < 768) ? w.p[11][(kk - 512) * 256 + nl] : 0.f;
        else
            x = (kk < 512) ? 0.f
              : (kk < 768) ? w.p[12][(kk - 512) * 256 + nl]
                           : w.p[14][(kk - 768) * 256 + nl];
    }
    __nv_bfloat16 h = __float2bfloat16(x);
    g_Wh[idx] = h;
    g_Wl[idx] = __float2bfloat16(x - __bfloat162float(h));
}

// --------------- fused softmax + text = P . S --------------------------------
__global__ void __launch_bounds__(256)
text_softmax(const float* __restrict__ S, const float* __restrict__ sc,
             float* __restrict__ P, float* __restrict__ text)
{
    const int b = blockIdx.x, tid = threadIdx.x;
    __shared__ float sp[MM];

    if (tid < 32) {
        float s0 = sc[b * MM + tid];
        float s1 = (tid < 18) ? sc[b * MM + tid + 32] : -1e30f;
        float mx = fmaxf(s0, s1);
#pragma unroll
        for (int off = 16; off > 0; off >>= 1)
            mx = fmaxf(mx, __shfl_xor_sync(0xffffffffu, mx, off));
        float e0 = expf(s0 - mx);
        float e1 = (tid < 18) ? expf(s1 - mx) : 0.f;
        float sum = e0 + e1;
#pragma unroll
        for (int off = 16; off > 0; off >>= 1)
            sum += __shfl_xor_sync(0xffffffffu, sum, off);
        float inv = 1.f / sum;
        sp[tid] = e0 * inv;
        P[b * MM + tid] = e0 * inv;
        if (tid < 18) { sp[tid + 32] = e1 * inv; P[b * MM + tid + 32] = e1 * inv; }
    }
    __syncthreads();

    const float* Sb = S + (size_t)b * MM * UU;
    float a = 0.f;
#pragma unroll 5
    for (int m = 0; m < MM; m++)
        a = fmaf(sp[m], Sb[m * UU + tid], a);
    text[(size_t)b * UU + tid] = a;
}

// ---------------- elementwise combines ---------------------------------------
__global__ void __launch_bounds__(256)
vcomb_kernel(const float* __restrict__ F, const float* __restrict__ O,
             const float* __restrict__ T, const float* __restrict__ v,
             float* __restrict__ V)
{
    int i = blockIdx.x * 256 + threadIdx.x;
    V[i] = fmaf(F[i], v[i], O[i] * T[i]);
}

__global__ void __launch_bounds__(256)
hcomb_kernel(const float* __restrict__ k, const float* __restrict__ hv,
             const float* __restrict__ hx, float* __restrict__ H)
{
    int i = blockIdx.x * 256 + threadIdx.x;
    float kk = k[i];
    H[i] = fmaf(1.f - kk, hv[i], kk * hx[i]);
}

// ---------------- launch ------------------------------------------------------
extern "C" void kernel_launch(void* const* d_in, const int* in_sizes, int n_in,
                              void* d_out, int out_size)
{
    const float* X    = (const float*)d_in[0];
    const float* S    = (const float*)d_in[1];
    const float* h    = (const float*)d_in[2];
    const float* v    = (const float*)d_in[3];
    const float* W_sa = (const float*)d_in[4];
    const float* W_ha = (const float*)d_in[5];
    const float* b_a  = (const float*)d_in[6];
    const float* v_a  = (const float*)d_in[7];
    const float* W_f  = (const float*)d_in[8];
    const float* W_hf = (const float*)d_in[9];
    const float* b_f  = (const float*)d_in[10];
    const float* W_o  = (const float*)d_in[11];
    const float* W_ho = (const float*)d_in[12];
    const float* b_o  = (const float*)d_in[13];
    const float* W_t  = (const float*)d_in[14];
    const float* W_ht = (const float*)d_in[15];
    const float* b_t  = (const float*)d_in[16];
    const float* W_k  = (const float*)d_in[17];
    const float* W_hk = (const float*)d_in[18];
    const float* W_vk = (const float*)d_in[19];
    const float* b_k  = (const float*)d_in[20];
    const float* W_s  = (const float*)d_in[21];
    const float* W_hs = (const float*)d_in[22];
    const float* b_s  = (const float*)d_in[23];
    const float* W_v  = (const float*)d_in[24];
    const float* W_hv = (const float*)d_in[25];
    const float* b_v  = (const float*)d_in[26];

    float* outH = (float*)d_out;
    float* outP = outH + (size_t)B_ * UU;
    float* outV = outP + (size_t)B_ * MM;

    float *hb, *scores, *text, *Fb, *Ob, *Tb;
    cudaGetSymbolAddress((void**)&hb,     g_hb);
    cudaGetSymbolAddress((void**)&scores, g_scores);
    cudaGetSymbolAddress((void**)&text,   g_text);
    cudaGetSymbolAddress((void**)&Fb,     g_F);
    cudaGetSymbolAddress((void**)&Ob,     g_O);
    cudaGetSymbolAddress((void**)&Tb,     g_T);

    cudaFuncSetAttribute(attn_scores_tc2,
                         cudaFuncAttributeMaxDynamicSharedMemorySize, SC_SMEM);
    cudaFuncSetAttribute(gate_mma,
                         cudaFuncAttributeMaxDynamicSharedMemorySize, SMEM_MMA);

    // 0. weight prep into regions
    WPtrs wp;
    wp.p[0] = W_sa; wp.p[1] = W_ha; wp.p[2] = W_f;  wp.p[3] = W_o;
    wp.p[4] = W_t;  wp.p[5] = W_hf; wp.p[6] = W_ho; wp.p[7] = W_ht;
    wp.p[8] = W_k;  wp.p[9] = W_s;  wp.p[10] = W_hk; wp.p[11] = W_hs;
    wp.p[12] = W_hv; wp.p[13] = W_vk; wp.p[14] = W_v;
    wprep_all<<<WTOT / 256, 256>>>(wp);

    GateArgs ga;
    ga.text = text; ga.h = h; ga.X = X; ga.V = outV;
    ga.ba = b_a; ga.bf = b_f; ga.bo = b_o; ga.bt = b_t;
    ga.bk = b_k; ga.bs = b_s; ga.bv = b_v;
    ga.hb = hb; ga.F = Fb; ga.O = Ob; ga.T = Tb;

    const int ewBlocks = (B_ * UU) / 256;

    // 1. hb = h @ W_ha + b_a
    gate_mma<<<dim3(B_ / 64, 2), 256, SMEM_MMA>>>(ga, 0);
    // 2. scores (pipelined tcgen-less HMMA, fused tanh + dot v_a)
    attn_scores_tc2<<<BMROWS / 128, 512, SC_SMEM>>>(S, hb, v_a, scores);
    // 3. P = softmax(scores); text = P . S   (fused)
    text_softmax<<<B_, 256>>>(S, scores, outP, text);
    // 4. F, O, T in one launch
    gate_mma<<<dim3(B_ / 64, 6), 256, SMEM_MMA>>>(ga, 1);
    // 5. V = F*v + O*text_new
    vcomb_kernel<<<ewBlocks, 256>>>(Fb, Ob, Tb, v, outV);
    // 6. k, hx, hv in one launch (k->Fb, hx->Ob, hv->Tb)
    gate_mma<<<dim3(B_ / 64, 6), 256, SMEM_MMA>>>(ga, 2);
    // 7. H = (1-k)*hv + k*hx
    hcomb_kernel<<<ewBlocks, 256>>>(Fb, Tb, Ob, outH);
}

// round 9
// speedup vs baseline: 1.0032x; 1.0026x over previous
#include <cuda_runtime.h>
#include <cuda_bf16.h>
#include <math.h>
#include <cstdint>

// Problem constants
#define B_     8192
#define DIN    512
#define UU     256
#define MM     50
#define BMROWS (B_ * MM)     // 409600

// ---------------- scratch (device globals; no allocation allowed) ----------
__device__ float g_hb[B_ * UU];
__device__ float g_scores[BMROWS];
__device__ float g_text[B_ * UU];
__device__ float g_F[B_ * UU];
__device__ float g_O[B_ * UU];
__device__ float g_T[B_ * UU];

// prepped weights, bf16 hi/lo, [N][K] row-major regions:
//   OW_SA  [256][256]   W_sa^T
//   OW_HA  [256][256]   W_ha^T
//   OW_FOT [768][512]   n: F|O|T,  k: text(256)|h(256)
//   OW_KHH [768][1024]  n: k|hx|hv, k: X(512)|h(256)|V(256)
#define OW_SA  0
#define OW_HA  65536
#define OW_FOT 131072
#define OW_KHH 524288
#define WTOT   1310720
__device__ __nv_bfloat16 g_Wh[WTOT];
__device__ __nv_bfloat16 g_Wl[WTOT];

// ======================= low-level helpers ==================================
static __device__ __forceinline__ uint32_t smem_u32(const void* p) {
    uint32_t a;
    asm("{ .reg .u64 t; cvta.to.shared.u64 t, %1; cvt.u32.u64 %0, t; }"
        : "=r"(a) : "l"(p));
    return a;
}

static __device__ __forceinline__ void ldsm4(uint32_t* r, uint32_t a) {
    asm volatile("ldmatrix.sync.aligned.m8n8.x4.shared.b16 {%0,%1,%2,%3}, [%4];"
                 : "=r"(r[0]), "=r"(r[1]), "=r"(r[2]), "=r"(r[3]) : "r"(a));
}

static __device__ __forceinline__ void mma_bf16(float* c, const uint32_t* a,
                                                const uint32_t* b) {
    asm volatile(
        "mma.sync.aligned.m16n8k16.row.col.f32.bf16.bf16.f32 "
        "{%0,%1,%2,%3}, {%4,%5,%6,%7}, {%8,%9}, {%0,%1,%2,%3};"
        : "+f"(c[0]), "+f"(c[1]), "+f"(c[2]), "+f"(c[3])
        : "r"(a[0]), "r"(a[1]), "r"(a[2]), "r"(a[3]), "r"(b[0]), "r"(b[1]));
}

#define CP16(dst, src) \
    asm volatile("cp.async.cg.shared.global [%0], [%1], 16;" \
                 :: "r"(dst), "l"(src) : "memory")
#define CPCOMMIT() asm volatile("cp.async.commit_group;" ::: "memory")
#define CPWAIT0()  asm volatile("cp.async.wait_group 0;" ::: "memory")

static __device__ __forceinline__ float fast_tanh(float x) {
    float e = __expf(2.f * x);
    return 1.f - __fdividef(2.f, e + 1.f);
}
static __device__ __forceinline__ float fast_sig(float x) {
    return __fdividef(1.f, 1.f + __expf(-x));
}

// =================== SCORES kernel (pipelined, full-N) =======================
// BM=128, BN=256, BK=32, 512 threads (16 warps 4x4), warp tile 32x64.
// SMEM: A stages @ 0 (2 x 20480: hi 10240 + lo 10240), B stages @ 40960
// (2 x 40960: hi 20480 + lo 20480). Row = 32 bf16 + 8 pad = 80 B.
#define SC_SA(s)  ((s) * 20480)
#define SC_SAL    10240
#define SC_SB(s)  (40960 + (s) * 40960)
#define SC_SBL    20480
#define SC_SMEM   122880

static __device__ __forceinline__ void sc_storeA(
    char* smem, uint32_t stage, uint32_t o0, uint32_t o1, float4 f0, float4 f1)
{
    const uint32_t base = SC_SA(stage);
#pragma unroll
    for (int q = 0; q < 2; q++) {
        float4 f = q ? f1 : f0;
        uint32_t off = q ? o1 : o0;
        __nv_bfloat16 h0 = __float2bfloat16(f.x);
        __nv_bfloat16 h1 = __float2bfloat16(f.y);
        __nv_bfloat16 h2 = __float2bfloat16(f.z);
        __nv_bfloat16 h3 = __float2bfloat16(f.w);
        __nv_bfloat16 l0 = __float2bfloat16(f.x - __bfloat162float(h0));
        __nv_bfloat16 l1 = __float2bfloat16(f.y - __bfloat162float(h1));
        __nv_bfloat16 l2 = __float2bfloat16(f.z - __bfloat162float(h2));
        __nv_bfloat16 l3 = __float2bfloat16(f.w - __bfloat162float(h3));
        uint2 uh, ul;
        uh.x = (uint32_t)__bfloat16_as_ushort(h0) |
               ((uint32_t)__bfloat16_as_ushort(h1) << 16);
        uh.y = (uint32_t)__bfloat16_as_ushort(h2) |
               ((uint32_t)__bfloat16_as_ushort(h3) << 16);
        ul.x = (uint32_t)__bfloat16_as_ushort(l0) |
               ((uint32_t)__bfloat16_as_ushort(l1) << 16);
        ul.y = (uint32_t)__bfloat16_as_ushort(l2) |
               ((uint32_t)__bfloat16_as_ushort(l3) << 16);
        *(uint2*)(smem + base + off) = uh;
        *(uint2*)(smem + base + SC_SAL + off) = ul;
    }
}

static __device__ __forceinline__ void sc_cpB(
    uint32_t sb, uint32_t stage, int k0, int bn, int bseg)
{
    uint32_t d = sb + SC_SB(stage);
    const __nv_bfloat16* sh = g_Wh + OW_SA;
    const __nv_bfloat16* sl = g_Wl + OW_SA;
    CP16(d + bn * 80 + bseg * 16,           sh + bn * 256 + k0 + bseg * 8);
    CP16(d + (bn + 128) * 80 + bseg * 16,   sh + (bn + 128) * 256 + k0 + bseg * 8);
    CP16(d + SC_SBL + bn * 80 + bseg * 16,  sl + bn * 256 + k0 + bseg * 8);
    CP16(d + SC_SBL + (bn + 128) * 80 + bseg * 16,
         sl + (bn + 128) * 256 + k0 + bseg * 8);
}

static __device__ __forceinline__ void sc_mma32(
    float (&acc)[2][8][4], uint32_t aA, uint32_t bB, uint32_t akb, uint32_t bkb)
{
#pragma unroll
    for (int kk = 0; kk < 2; kk++) {
        uint32_t ah[2][4], al[2][4];
        uint32_t aoff = (kk * 16 + akb) * 2;
        ldsm4(ah[0], aA + aoff);
        ldsm4(ah[1], aA + 1280 + aoff);
        ldsm4(al[0], aA + SC_SAL + aoff);
        ldsm4(al[1], aA + SC_SAL + 1280 + aoff);
        uint32_t boff = (kk * 16 + bkb) * 2;
#pragma unroll
        for (int g = 0; g < 4; g++) {
            uint32_t tb[4], tl[4];
            ldsm4(tb, bB + g * 1280 + boff);
            ldsm4(tl, bB + SC_SBL + g * 1280 + boff);
            uint32_t b0h[2] = {tb[0], tb[1]}, b1h[2] = {tb[2], tb[3]};
            uint32_t b0l[2] = {tl[0], tl[1]}, b1l[2] = {tl[2], tl[3]};
#pragma unroll
            for (int mi = 0; mi < 2; mi++) {
                mma_bf16(acc[mi][2 * g],     ah[mi], b0h);
                mma_bf16(acc[mi][2 * g],     al[mi], b0h);
                mma_bf16(acc[mi][2 * g],     ah[mi], b0l);
                mma_bf16(acc[mi][2 * g + 1], ah[mi], b1h);
                mma_bf16(acc[mi][2 * g + 1], al[mi], b1h);
                mma_bf16(acc[mi][2 * g + 1], ah[mi], b1l);
            }
        }
    }
}

__global__ void __launch_bounds__(512, 1)
attn_scores_tc2(const float* __restrict__ S, const float* __restrict__ hb,
                const float* __restrict__ va, float* __restrict__ scores)
{
    extern __shared__ char smem[];
    const uint32_t sb = smem_u32(smem);
    const int tid = threadIdx.x, lane = tid & 31, wid = tid >> 5;
    const int warpM = wid >> 2, warpN = wid & 3;
    const int row0 = blockIdx.x * 128;

    float acc[2][8][4];
#pragma unroll
    for (int a = 0; a < 2; a++)
#pragma unroll
        for (int b = 0; b < 8; b++)
#pragma unroll
            for (int c = 0; c < 4; c++) acc[a][b][c] = 0.f;

    const uint32_t arow = warpM * 32 + ((lane >> 3) & 1) * 8 + (lane & 7);
    const uint32_t akb  = ((lane >> 4) & 1) * 8;
    const uint32_t brow = warpN * 64 + ((lane >> 4) & 1) * 8 + (lane & 7);
    const uint32_t bkb  = ((lane >> 3) & 1) * 8;

    // A ldg mapping: idx = tid (+512) -> r = idx>>3, c4 = idx&7
    const int r0i = tid >> 3, c4 = tid & 7;
    const float* gA0 = S + (size_t)(row0 + r0i) * UU + c4 * 4;
    const float* gA1 = gA0 + (size_t)64 * UU;
    const uint32_t stA0 = r0i * 80 + c4 * 8;
    const uint32_t stA1 = stA0 + 64 * 80;
    // B cp.async mapping: idx = tid -> n = tid>>2, seg = tid&3 (plus n+128)
    const int bn = tid >> 2, bseg = tid & 3;

    // prologue: chunk 0
    float4 pf0 = *(const float4*)(gA0);
    float4 pf1 = *(const float4*)(gA1);
    sc_cpB(sb, 0, 0, bn, bseg);
    CPCOMMIT();
    sc_storeA(smem, 0, stA0, stA1, pf0, pf1);
    CPWAIT0();
    __syncthreads();

    for (int c = 0; c < 8; c++) {
        const int cur = c & 1, nxt = cur ^ 1;
        if (c < 7) {
            const int k0 = (c + 1) * 32;
            pf0 = *(const float4*)(gA0 + k0);
            pf1 = *(const float4*)(gA1 + k0);
            sc_cpB(sb, nxt, k0, bn, bseg);
            CPCOMMIT();
        }
        sc_mma32(acc, sb + SC_SA(cur) + arow * 80,
                 sb + SC_SB(cur) + brow * 80, akb, bkb);
        if (c < 7) {
            sc_storeA(smem, nxt, stA0, stA1, pf0, pf1);
            CPWAIT0();
        }
        __syncthreads();
    }

    // ---- epilogue: tanh + dot(v_a) reduce over full N=256 -------------------
    float* red = (float*)smem;                 // [128][4]
    float* sHB = (float*)(smem + 2048);        // [4][256]
    float* sVA = (float*)(smem + 6144);        // [256]
    const int b_first = row0 / MM;
    for (int i = tid; i < 1024; i += 512) {
        int j = i >> 8, cc = i & 255;
        int bb = b_first + j; if (bb > B_ - 1) bb = B_ - 1;
        sHB[i] = hb[(size_t)bb * UU + cc];
    }
    if (tid < 256) sVA[tid] = va[tid];
    __syncthreads();

#pragma unroll
    for (int mi = 0; mi < 2; mi++)
#pragma unroll
        for (int hf = 0; hf < 2; hf++) {
            const int rloc = warpM * 32 + mi * 16 + (lane >> 2) + hf * 8;
            const int bj = (row0 + rloc) / MM - b_first;
            const float* hrow = sHB + bj * 256;
            float p = 0.f;
#pragma unroll
            for (int ni = 0; ni < 8; ni++) {
                const int cc = warpN * 64 + ni * 8 + (lane & 3) * 2;
                p += fast_tanh(acc[mi][ni][hf * 2] + hrow[cc]) * sVA[cc];
                p += fast_tanh(acc[mi][ni][hf * 2 + 1] + hrow[cc + 1]) * sVA[cc + 1];
            }
            p += __shfl_xor_sync(0xffffffffu, p, 1);
            p += __shfl_xor_sync(0xffffffffu, p, 2);
            if ((lane & 3) == 0) red[rloc * 4 + warpN] = p;
        }
    __syncthreads();
    if (tid < 128)
        scores[row0 + tid] = red[tid * 4] + red[tid * 4 + 1] +
                             red[tid * 4 + 2] + red[tid * 4 + 3];
}

// =================== GATE kernels (round-3 machinery, y-fused) ===============
#define LDS_ROW 72
#define SA_H 0
#define SA_L 9216
#define SB_H 18432
#define SB_L 36864
#define SMEM_MMA 55296

static __device__ __forceinline__ void load_Atile(
    const float* __restrict__ A, int K, int row0, int k0, char* smem, int tid)
{
#pragma unroll
    for (int i = 0; i < 4; i++) {
        int idx = tid + (i << 8);
        int r = idx >> 4, c4 = idx & 15;
        float4 f = *(const float4*)(A + (size_t)(row0 + r) * K + k0 + (c4 << 2));
        __nv_bfloat16 h0 = __float2bfloat16(f.x);
        __nv_bfloat16 h1 = __float2bfloat16(f.y);
        __nv_bfloat16 h2 = __float2bfloat16(f.z);
        __nv_bfloat16 h3 = __float2bfloat16(f.w);
        __nv_bfloat16 l0 = __float2bfloat16(f.x - __bfloat162float(h0));
        __nv_bfloat16 l1 = __float2bfloat16(f.y - __bfloat162float(h1));
        __nv_bfloat16 l2 = __float2bfloat16(f.z - __bfloat162float(h2));
        __nv_bfloat16 l3 = __float2bfloat16(f.w - __bfloat162float(h3));
        uint2 uh, ul;
        uh.x = (uint32_t)__bfloat16_as_ushort(h0) |
               ((uint32_t)__bfloat16_as_ushort(h1) << 16);
        uh.y = (uint32_t)__bfloat16_as_ushort(h2) |
               ((uint32_t)__bfloat16_as_ushort(h3) << 16);
        ul.x = (uint32_t)__bfloat16_as_ushort(l0) |
               ((uint32_t)__bfloat16_as_ushort(l1) << 16);
        ul.y = (uint32_t)__bfloat16_as_ushort(l2) |
               ((uint32_t)__bfloat16_as_ushort(l3) << 16);
        uint32_t off = (uint32_t)(r * LDS_ROW + (c4 << 2)) * 2;
        *(uint2*)(smem + SA_H + off) = uh;
        *(uint2*)(smem + SA_L + off) = ul;
    }
}

static __device__ __forceinline__ void load_Btile(
    int woff, int K, int n0, int k0, char* smem, int tid)
{
    const __nv_bfloat16* Bh = g_Wh + woff;
    const __nv_bfloat16* Bl = g_Wl + woff;
#pragma unroll
    for (int i = 0; i < 8; i++) {
        int idx = tid + (i << 8);
        int r = idx >> 4, u = idx & 15;
        uint2 vh = *(const uint2*)(Bh + (size_t)(n0 + r) * K + k0 + (u << 2));
        uint2 vl = *(const uint2*)(Bl + (size_t)(n0 + r) * K + k0 + (u << 2));
        uint32_t off = (uint32_t)(r * LDS_ROW + (u << 2)) * 2;
        *(uint2*)(smem + SB_H + off) = vh;
        *(uint2*)(smem + SB_L + off) = vl;
    }
}

static __device__ __forceinline__ void mma_chunk(
    float (&acc)[2][4][4], uint32_t sb, int warpM, int warpN, int lane)
{
    const int arow = warpM * 32 + ((lane >> 3) & 1) * 8 + (lane & 7);
    const int brow = warpN * 32 + ((lane >> 4) & 1) * 8 + (lane & 7);
    const uint32_t akb = ((lane >> 4) & 1) * 8;
    const uint32_t bkb = ((lane >> 3) & 1) * 8;
    const uint32_t aBase = sb + (uint32_t)(arow * LDS_ROW) * 2;
    const uint32_t bBase = sb + (uint32_t)(brow * LDS_ROW) * 2;

#pragma unroll
    for (int kk = 0; kk < 4; kk++) {
        uint32_t ah[2][4], al[2][4];
        uint32_t aoff = (kk * 16 + akb) * 2;
        ldsm4(ah[0], aBase + SA_H + aoff);
        ldsm4(ah[1], aBase + SA_H + aoff + 16 * LDS_ROW * 2);
        ldsm4(al[0], aBase + SA_L + aoff);
        ldsm4(al[1], aBase + SA_L + aoff + 16 * LDS_ROW * 2);

        uint32_t boff = (kk * 16 + bkb) * 2;
        uint32_t t[4], u[4], tl[4], ul2[4];
        ldsm4(t,   bBase + SB_H + boff);
        ldsm4(u,   bBase + SB_H + boff + 16 * LDS_ROW * 2);
        ldsm4(tl,  bBase + SB_L + boff);
        ldsm4(ul2, bBase + SB_L + boff + 16 * LDS_ROW * 2);
        uint32_t bh[4][2] = {{t[0], t[1]}, {t[2], t[3]}, {u[0], u[1]}, {u[2], u[3]}};
        uint32_t bl[4][2] = {{tl[0], tl[1]}, {tl[2], tl[3]}, {ul2[0], ul2[1]}, {ul2[2], ul2[3]}};
#pragma unroll
        for (int ni = 0; ni < 4; ni++) {
#pragma unroll
            for (int mi = 0; mi < 2; mi++) {
                mma_bf16(acc[mi][ni], ah[mi], bh[ni]);
                mma_bf16(acc[mi][ni], al[mi], bh[ni]);
                mma_bf16(acc[mi][ni], ah[mi], bl[ni]);
            }
        }
    }
}

struct GateArgs {
    const float *text, *h, *X, *V;
    const float *ba, *bf, *bo, *bt, *bk, *bs, *bv;
    float *hb, *F, *O, *T;
};

__global__ void __launch_bounds__(256)
gate_mma(GateArgs g, int mode)
{
    extern __shared__ char smem[];
    const uint32_t sb = smem_u32(smem);
    const int tid = threadIdx.x, lane = tid & 31, wid = tid >> 5;
    const int warpM = wid >> 2, warpN = wid & 3;
    const int y = blockIdx.y;
    const int out = (mode == 0) ? 0 : (y >> 1);
    const int nh  = (mode == 0) ? y : (y & 1);
    const int row0 = blockIdx.x * 64;
    const int nloc0 = nh * 128;

    int region, Kfull, nglob0, cs = 0, ce;
    if (mode == 0)      { region = OW_HA;  Kfull = 256;  nglob0 = nloc0; ce = 4; }
    else if (mode == 1) { region = OW_FOT; Kfull = 512;  nglob0 = out * 256 + nloc0; ce = 8; }
    else                { region = OW_KHH; Kfull = 1024; nglob0 = out * 256 + nloc0;
                          ce = (out == 1) ? 12 : 16; cs = (out == 2) ? 8 : 0; }

    float acc[2][4][4];
#pragma unroll
    for (int a = 0; a < 2; a++)
#pragma unroll
        for (int b = 0; b < 4; b++)
#pragma unroll
            for (int c = 0; c < 4; c++) acc[a][b][c] = 0.f;

    for (int cc = cs; cc < ce; cc++) {
        const float* A; int KA, kloc;
        if (mode == 0)      { A = g.h; KA = 256; kloc = cc * 64; }
        else if (mode == 1) {
            if (cc < 4) { A = g.text; KA = 256; kloc = cc * 64; }
            else        { A = g.h;    KA = 256; kloc = (cc - 4) * 64; }
        } else {
            if (cc < 8)       { A = g.X; KA = 512; kloc = cc * 64; }
            else if (cc < 12) { A = g.h; KA = 256; kloc = (cc - 8) * 64; }
            else              { A = g.V; KA = 256; kloc = (cc - 12) * 64; }
        }
        load_Atile(A, KA, row0, kloc, smem, tid);
        load_Btile(region, Kfull, nglob0, cc * 64, smem, tid);
        __syncthreads();
        mma_chunk(acc, sb, warpM, warpN, lane);
        __syncthreads();
    }

    const float* bias; float* outp; int act;
    if (mode == 0)      { bias = g.ba; outp = g.hb; act = 0; }
    else if (mode == 1) {
        if (out == 0)      { bias = g.bf; outp = g.F; act = 1; }
        else if (out == 1) { bias = g.bo; outp = g.O; act = 1; }
        else               { bias = g.bt; outp = g.T; act = 2; }
    } else {
        if (out == 0)      { bias = g.bk; outp = g.F; act = 1; }
        else if (out == 1) { bias = g.bs; outp = g.O; act = 2; }
        else               { bias = g.bv; outp = g.T; act = 2; }
    }

#pragma unroll
    for (int mi = 0; mi < 2; mi++)
#pragma unroll
        for (int ni = 0; ni < 4; ni++) {
            int c = nloc0 + warpN * 32 + ni * 8 + (lane & 3) * 2;
            float b0 = bias[c], b1 = bias[c + 1];
            int r = row0 + warpM * 32 + mi * 16 + (lane >> 2);
#pragma unroll
            for (int hf = 0; hf < 2; hf++) {
                float x0 = acc[mi][ni][hf * 2 + 0] + b0;
                float x1 = acc[mi][ni][hf * 2 + 1] + b1;
                if (act == 1)      { x0 = fast_sig(x0);  x1 = fast_sig(x1); }
                else if (act == 2) { x0 = fast_tanh(x0); x1 = fast_tanh(x1); }
                *(float2*)(outp + (size_t)(r + hf * 8) * UU + c) =
                    make_float2(x0, x1);
            }
        }
}

// ---------------- weight prep -------------------------------------------------
struct WPtrs { const float* p[15]; };
// p: 0 W_sa, 1 W_ha, 2 W_f, 3 W_o, 4 W_t, 5 W_hf, 6 W_ho, 7 W_ht,
//    8 W_k, 9 W_s, 10 W_hk, 11 W_hs, 12 W_hv, 13 W_vk, 14 W_v

__global__ void __launch_bounds__(256)
wprep_all(WPtrs w)
{
    int idx = blockIdx.x * 256 + threadIdx.x;
    float x;
    if (idx < 65536) {
        int n = idx >> 8, kk = idx & 255;
        x = w.p[0][kk * 256 + n];
    } else if (idx < 131072) {
        int l = idx - 65536; int n = l >> 8, kk = l & 255;
        x = w.p[1][kk * 256 + n];
    } else if (idx < 524288) {
        int l = idx - 131072; int n = l >> 9, kk = l & 511;
        int out = n >> 8, nl = n & 255;
        const float* Wa = (out == 0) ? w.p[2] : (out == 1) ? w.p[3] : w.p[4];
        const float* Wb = (out == 0) ? w.p[5] : (out == 1) ? w.p[6] : w.p[7];
        x = (kk < 256) ? Wa[kk * 256 + nl] : Wb[(kk - 256) * 256 + nl];
    } else {
        int l = idx - 524288; int n = l >> 10, kk = l & 1023;
        int out = n >> 8, nl = n & 255;
        if (out == 0)
            x = (kk < 512) ? w.p[8][kk * 256 + nl]
              : (kk < 768) ? w.p[10][(kk - 512) * 256 + nl]
                           : w.p[13][(kk - 768) * 256 + nl];
        else if (out == 1)
            x = (kk < 512) ? w.p[9][kk * 256 + nl]
              : (kk < 768) ? w.p[11][(kk - 512) * 256 + nl] : 0.f;
        else
            x = (kk < 512) ? 0.f
              : (kk < 768) ? w.p[12][(kk - 512) * 256 + nl]
                           : w.p[14][(kk - 768) * 256 + nl];
    }
    __nv_bfloat16 h = __float2bfloat16(x);
    g_Wh[idx] = h;
    g_Wl[idx] = __float2bfloat16(x - __bfloat162float(h));
}

// --------------- fused softmax + text = P . S --------------------------------
__global__ void __launch_bounds__(256)
text_softmax(const float* __restrict__ S, const float* __restrict__ sc,
             float* __restrict__ P, float* __restrict__ text)
{
    const int b = blockIdx.x, tid = threadIdx.x;
    __shared__ float sp[MM];

    if (tid < 32) {
        float s0 = sc[b * MM + tid];
        float s1 = (tid < 18) ? sc[b * MM + tid + 32] : -1e30f;
        float mx = fmaxf(s0, s1);
#pragma unroll
        for (int off = 16; off > 0; off >>= 1)
            mx = fmaxf(mx, __shfl_xor_sync(0xffffffffu, mx, off));
        float e0 = expf(s0 - mx);
        float e1 = (tid < 18) ? expf(s1 - mx) : 0.f;
        float sum = e0 + e1;
#pragma unroll
        for (int off = 16; off > 0; off >>= 1)
            sum += __shfl_xor_sync(0xffffffffu, sum, off);
        float inv = 1.f / sum;
        sp[tid] = e0 * inv;
        P[b * MM + tid] = e0 * inv;
        if (tid < 18) { sp[tid + 32] = e1 * inv; P[b * MM + tid + 32] = e1 * inv; }
    }
    __syncthreads();

    const float* Sb = S + (size_t)b * MM * UU;
    float a = 0.f;
#pragma unroll 5
    for (int m = 0; m < MM; m++)
        a = fmaf(sp[m], Sb[m * UU + tid], a);
    text[(size_t)b * UU + tid] = a;
}

// ---------------- elementwise combines ---------------------------------------
__global__ void __launch_bounds__(256)
vcomb_kernel(const float* __restrict__ F, const float* __restrict__ O,
             const float* __restrict__ T, const float* __restrict__ v,
             float* __restrict__ V)
{
    int i = blockIdx.x * 256 + threadIdx.x;
    V[i] = fmaf(F[i], v[i], O[i] * T[i]);
}

__global__ void __launch_bounds__(256)
hcomb_kernel(const float* __restrict__ k, const float* __restrict__ hv,
             const float* __restrict__ hx, float* __restrict__ H)
{
    int i = blockIdx.x * 256 + threadIdx.x;
    float kk = k[i];
    H[i] = fmaf(1.f - kk, hv[i], kk * hx[i]);
}

// ---------------- launch ------------------------------------------------------
extern "C" void kernel_launch(void* const* d_in, const int* in_sizes, int n_in,
                              void* d_out, int out_size)
{
    const float* X    = (const float*)d_in[0];
    const float* S    = (const float*)d_in[1];
    const float* h    = (const float*)d_in[2];
    const float* v    = (const float*)d_in[3];
    const float* W_sa = (const float*)d_in[4];
    const float* W_ha = (const float*)d_in[5];
    const float* b_a  = (const float*)d_in[6];
    const float* v_a  = (const float*)d_in[7];
    const float* W_f  = (const float*)d_in[8];
    const float* W_hf = (const float*)d_in[9];
    const float* b_f  = (const float*)d_in[10];
    const float* W_o  = (const float*)d_in[11];
    const float* W_ho = (const float*)d_in[12];
    const float* b_o  = (const float*)d_in[13];
    const float* W_t  = (const float*)d_in[14];
    const float* W_ht = (const float*)d_in[15];
    const float* b_t  = (const float*)d_in[16];
    const float* W_k  = (const float*)d_in[17];
    const float* W_hk = (const float*)d_in[18];
    const float* W_vk = (const float*)d_in[19];
    const float* b_k  = (const float*)d_in[20];
    const float* W_s  = (const float*)d_in[21];
    const float* W_hs = (const float*)d_in[22];
    const float* b_s  = (const float*)d_in[23];
    const float* W_v  = (const float*)d_in[24];
    const float* W_hv = (const float*)d_in[25];
    const float* b_v  = (const float*)d_in[26];

    float* outH = (float*)d_out;
    float* outP = outH + (size_t)B_ * UU;
    float* outV = outP + (size_t)B_ * MM;

    float *hb, *scores, *text, *Fb, *Ob, *Tb;
    cudaGetSymbolAddress((void**)&hb,     g_hb);
    cudaGetSymbolAddress((void**)&scores, g_scores);
    cudaGetSymbolAddress((void**)&text,   g_text);
    cudaGetSymbolAddress((void**)&Fb,     g_F);
    cudaGetSymbolAddress((void**)&Ob,     g_O);
    cudaGetSymbolAddress((void**)&Tb,     g_T);

    cudaFuncSetAttribute(attn_scores_tc2,
                         cudaFuncAttributeMaxDynamicSharedMemorySize, SC_SMEM);
    cudaFuncSetAttribute(gate_mma,
                         cudaFuncAttributeMaxDynamicSharedMemorySize, SMEM_MMA);

    // 0. weight prep into regions
    WPtrs wp;
    wp.p[0] = W_sa; wp.p[1] = W_ha; wp.p[2] = W_f;  wp.p[3] = W_o;
    wp.p[4] = W_t;  wp.p[5] = W_hf; wp.p[6] = W_ho; wp.p[7] = W_ht;
    wp.p[8] = W_k;  wp.p[9] = W_s;  wp.p[10] = W_hk; wp.p[11] = W_hs;
    wp.p[12] = W_hv; wp.p[13] = W_vk; wp.p[14] = W_v;
    wprep_all<<<WTOT / 256, 256>>>(wp);

    GateArgs ga;
    ga.text = text; ga.h = h; ga.X = X; ga.V = outV;
    ga.ba = b_a; ga.bf = b_f; ga.bo = b_o; ga.bt = b_t;
    ga.bk = b_k; ga.bs = b_s; ga.bv = b_v;
    ga.hb = hb; ga.F = Fb; ga.O = Ob; ga.T = Tb;

    const int ewBlocks = (B_ * UU) / 256;

    // 1. hb = h @ W_ha + b_a
    gate_mma<<<dim3(B_ / 64, 2), 256, SMEM_MMA>>>(ga, 0);
    // 2. scores (pipelined tcgen-less HMMA, fused tanh + dot v_a)
    attn_scores_tc2<<<BMROWS / 128, 512, SC_SMEM>>>(S, hb, v_a, scores);
    // 3. P = softmax(scores); text = P . S   (fused)
    text_softmax<<<B_, 256>>>(S, scores, outP, text);
    // 4. F, O, T in one launch
    gate_mma<<<dim3(B_ / 64, 6), 256, SMEM_MMA>>>(ga, 1);
    // 5. V = F*v + O*text_new
    vcomb_kernel<<<ewBlocks, 256>>>(Fb, Ob, Tb, v, outV);
    // 6. k, hx, hv in one launch (k->Fb, hx->Ob, hv->Tb)
    gate_mma<<<dim3(B_ / 64, 6), 256, SMEM_MMA>>>(ga, 2);
    // 7. H = (1-k)*hv + k*hx
    hcomb_kernel<<<ewBlocks, 256>>>(Fb, Tb, Ob, outH);
}